// round 12
// baseline (speedup 1.0000x reference)
#include <cuda_runtime.h>

// PDELayer: 100 diffusion steps, 48x48, 8192 batches, frozen reflect boundary.
// Round 11 (= R9 resubmit + left-neighbor staleness fix):
// BATCH-PAIR PACKING: each f32x2 register = same cell of two batches.
// Coefficients are batch-independent so all math is naturally packed:
// no parity MOVs, no scalar horizontal adds. 3.0 fma-inst/cell.
// CTA = 64 threads = 2 batches; thread tile 6x6 cells; seam smem + 1 bar/step.
// IMPORTANT: horizontal left neighbor must be the OLD value -> carried in
// 'leftold' through the row sweep (v[r][c-1] is already updated at that point).

#define NXY 48
#define NT  100

static __forceinline__ __device__ float2 f2add(float2 a, float2 b) {
    float2 d;
    asm("{\n\t.reg .b64 ra,rb,rd;\n\t"
        "mov.b64 ra,{%2,%3};\n\tmov.b64 rb,{%4,%5};\n\t"
        "add.rn.f32x2 rd, ra, rb;\n\t"
        "mov.b64 {%0,%1}, rd;\n\t}"
        : "=f"(d.x), "=f"(d.y)
        : "f"(a.x), "f"(a.y), "f"(b.x), "f"(b.y));
    return d;
}
static __forceinline__ __device__ float2 f2fma(float2 a, float2 b, float2 c) {
    float2 d;
    asm("{\n\t.reg .b64 ra,rb,rc,rd;\n\t"
        "mov.b64 ra,{%2,%3};\n\tmov.b64 rb,{%4,%5};\n\tmov.b64 rc,{%6,%7};\n\t"
        "fma.rn.f32x2 rd, ra, rb, rc;\n\t"
        "mov.b64 {%0,%1}, rd;\n\t}"
        : "=f"(d.x), "=f"(d.y)
        : "f"(a.x), "f"(a.y), "f"(b.x), "f"(b.y), "f"(c.x), "f"(c.y));
    return d;
}
static __forceinline__ __device__ float2 shfl_up2(float2 v, int delta) {
    float2 r;
    r.x = __shfl_up_sync(0xffffffffu, v.x, delta);
    r.y = __shfl_up_sync(0xffffffffu, v.y, delta);
    return r;
}
static __forceinline__ __device__ float2 shfl_dn2(float2 v, int delta) {
    float2 r;
    r.x = __shfl_down_sync(0xffffffffu, v.x, delta);
    r.y = __shfl_down_sync(0xffffffffu, v.y, delta);
    return r;
}

__global__ void __launch_bounds__(64, 6)
pde_kernel(const float* __restrict__ u0,
           const float* __restrict__ aw1, const float* __restrict__ aw2,
           const float* __restrict__ aw3, const float* __restrict__ bw1,
           const float* __restrict__ bw2, const float* __restrict__ bw3,
           float* __restrict__ out)
{
    __shared__ float2 seamA[2][48];   // grid row 23 (bottom of gr==3)
    __shared__ float2 seamB[2][48];   // grid row 24 (top of gr==4)

    const int tid   = threadIdx.x;
    const int warp  = tid >> 5;
    const int lane  = tid & 31;
    const int tcol  = lane & 7;        // 0..7 -> cols 6*tcol..6*tcol+5
    const int trow  = lane >> 3;       // 0..3
    const int gr    = warp * 4 + trow; // 0..7 -> rows 6*gr..6*gr+5

    const float* gA = u0  + (size_t)(2 * blockIdx.x)     * (NXY * NXY);
    const float* gB = u0  + (size_t)(2 * blockIdx.x + 1) * (NXY * NXY);
    float*       oA = out + (size_t)(2 * blockIdx.x)     * (NXY * NXY);
    float*       oB = out + (size_t)(2 * blockIdx.x + 1) * (NXY * NXY);

    // ---- coefficients (batch-independent, duplicated into both halves) ----
    const float TWO_PI = 6.283185307179586f;
    const float scale  = 1e-4f * 2304.0f;     // DT / DX^2
    const float inv47  = 1.0f / 47.0f;
    const float aa1 = fabsf(*aw1), aa2 = fabsf(*aw2), aa3 = fabsf(*aw3);
    const float bb1 = fabsf(*bw1), bb2 = fabsf(*bw2), bb3 = fabsf(*bw3);

    float2 a2[6];                      // alpha per local row
    #pragma unroll
    for (int r = 0; r < 6; r++) {
        float yv = (float)(6 * gr + r) * inv47;
        float al = 0.5f * scale * (aa1 + aa2 * sinf(TWO_PI * yv) + aa3 * cosf(TWO_PI * yv));
        a2[r] = make_float2(al, al);
    }
    float2 b2[6];                      // beta per local col
    #pragma unroll
    for (int c = 0; c < 6; c++) {
        float xv = (float)(6 * tcol + c) * inv47;
        float be = scale * (bb1 + bb2 * cosf(TWO_PI * xv) + bb3 * sinf(TWO_PI * xv));
        b2[c] = make_float2(be, be);
    }
    const float2 m2 = make_float2(-2.0f, -2.0f);

    // ---- load 6x6 cells, pack (batchA, batchB) per cell ----
    float2 v[6][6];
    #pragma unroll
    for (int r = 0; r < 6; r++) {
        const int eoff = (6 * gr + r) * 24 + tcol * 3;   // float2 element offset
        float2 lA0 = ((const float2*)gA)[eoff];
        float2 lA1 = ((const float2*)gA)[eoff + 1];
        float2 lA2 = ((const float2*)gA)[eoff + 2];
        float2 lB0 = ((const float2*)gB)[eoff];
        float2 lB1 = ((const float2*)gB)[eoff + 1];
        float2 lB2 = ((const float2*)gB)[eoff + 2];
        v[r][0] = make_float2(lA0.x, lB0.x);
        v[r][1] = make_float2(lA0.y, lB0.y);
        v[r][2] = make_float2(lA1.x, lB1.x);
        v[r][3] = make_float2(lA1.y, lB1.y);
        v[r][4] = make_float2(lA2.x, lB2.x);
        v[r][5] = make_float2(lA2.y, lB2.y);
    }

    // ---- frozen reflected boundary (initial values, constant for all steps) ----
    float2 fv[6];
    #pragma unroll
    for (int c = 0; c < 6; c++) fv[c] = (gr == 0) ? v[1][c] : v[4][c];
    float2 fh[6];
    #pragma unroll
    for (int r = 0; r < 6; r++) fh[r] = (tcol == 0) ? v[r][1] : v[r][4];

    const bool isTop = (gr == 0), isBot = (gr == 7);
    const bool sw0   = (gr == 3), sw1   = (gr == 4);
    const bool isL   = (tcol == 0), isR = (tcol == 7);
    const int  sidx  = tcol * 6;

    // ---- time loop ----
    #pragma unroll 2
    for (int t = 0; t < NT; t++) {
        const int buf = t & 1;
        if (sw0) {
            #pragma unroll
            for (int c = 0; c < 6; c++) seamA[buf][sidx + c] = v[5][c];
        }
        if (sw1) {
            #pragma unroll
            for (int c = 0; c < 6; c++) seamB[buf][sidx + c] = v[0][c];
        }
        __syncthreads();

        // halos (OLD state)
        float2 th[6], bh[6];
        #pragma unroll
        for (int c = 0; c < 6; c++) {
            float2 tu = shfl_up2(v[5][c], 8);
            float2 bd = shfl_dn2(v[0][c], 8);
            th[c] = isTop ? fv[c] : (sw1 ? seamA[buf][sidx + c] : tu);
            bh[c] = isBot ? fv[c] : (sw0 ? seamB[buf][sidx + c] : bd);
        }
        float2 lh[6], rh[6];
        #pragma unroll
        for (int r = 0; r < 6; r++) {
            float2 lu = shfl_up2(v[r][5], 1);
            float2 rd = shfl_dn2(v[r][0], 1);
            lh[r] = isL ? fh[r] : lu;
            rh[r] = isR ? fh[r] : rd;
        }

        // update: res = cur + a*(up+dn-2c) + b*(lf+rt-2c)   (all packed f2)
        // 'oldprev[c]' = OLD up neighbor; 'leftold' = OLD left neighbor.
        float2 oldprev[6];
        #pragma unroll
        for (int c = 0; c < 6; c++) oldprev[c] = th[c];
        #pragma unroll
        for (int r = 0; r < 6; r++) {
            float2 leftold = lh[r];
            #pragma unroll
            for (int c = 0; c < 6; c++) {
                float2 cur = v[r][c];
                float2 dn  = (r == 5) ? bh[c] : v[r + 1][c];
                float2 rt  = (c == 5) ? rh[r] : v[r][c + 1];
                float2 vs  = f2add(oldprev[c], dn);   // up + dn (both OLD)
                float2 hs  = f2add(leftold, rt);      // lf + rt (both OLD)
                vs = f2fma(m2, cur, vs);              // up+dn-2c
                hs = f2fma(m2, cur, hs);              // lf+rt-2c
                float2 res = f2fma(b2[c], hs, cur);   // c + b*hs
                res = f2fma(a2[r], vs, res);          // + a*vs
                oldprev[c] = cur;
                leftold    = cur;
                v[r][c] = res;
            }
        }
    }

    // ---- unpack & store ----
    #pragma unroll
    for (int r = 0; r < 6; r++) {
        const int eoff = (6 * gr + r) * 24 + tcol * 3;
        ((float2*)oA)[eoff]     = make_float2(v[r][0].x, v[r][1].x);
        ((float2*)oA)[eoff + 1] = make_float2(v[r][2].x, v[r][3].x);
        ((float2*)oA)[eoff + 2] = make_float2(v[r][4].x, v[r][5].x);
        ((float2*)oB)[eoff]     = make_float2(v[r][0].y, v[r][1].y);
        ((float2*)oB)[eoff + 1] = make_float2(v[r][2].y, v[r][3].y);
        ((float2*)oB)[eoff + 2] = make_float2(v[r][4].y, v[r][5].y);
    }
}

extern "C" void kernel_launch(void* const* d_in, const int* in_sizes, int n_in,
                              void* d_out, int out_size)
{
    const float* u0 = (const float*)d_in[0];
    int batches = in_sizes[0] / (NXY * NXY);
    int ctas = batches / 2;
    pde_kernel<<<ctas, 64>>>(u0,
        (const float*)d_in[1], (const float*)d_in[2], (const float*)d_in[3],
        (const float*)d_in[4], (const float*)d_in[5], (const float*)d_in[6],
        (float*)d_out);
}

// round 13
// speedup vs baseline: 1.5281x; 1.5281x over previous
#include <cuda_runtime.h>

// PDELayer: 100 diffusion steps, 48x48, 8192 batches, frozen reflect boundary.
// Round 12: OCCUPANCY PUSH. CTA = 128 threads = 1 batch (4 warps).
// Thread tile: 3 rows x 6 cols. Same proven R2 math (scalar hsums, f32x2
// vertical/combine, 7 fma-inst per column-pair). Warp seams via smem.
// Target ~80 regs -> 6+ warps/SMSP (R2 had 3.8 @ issue 63%).

#define NXY 48
#define NT  100

static __forceinline__ __device__ float2 f2add(float2 a, float2 b) {
    float2 d;
    asm("{\n\t.reg .b64 ra,rb,rd;\n\t"
        "mov.b64 ra,{%2,%3};\n\tmov.b64 rb,{%4,%5};\n\t"
        "add.rn.f32x2 rd, ra, rb;\n\t"
        "mov.b64 {%0,%1}, rd;\n\t}"
        : "=f"(d.x), "=f"(d.y)
        : "f"(a.x), "f"(a.y), "f"(b.x), "f"(b.y));
    return d;
}
static __forceinline__ __device__ float2 f2fma(float2 a, float2 b, float2 c) {
    float2 d;
    asm("{\n\t.reg .b64 ra,rb,rc,rd;\n\t"
        "mov.b64 ra,{%2,%3};\n\tmov.b64 rb,{%4,%5};\n\tmov.b64 rc,{%6,%7};\n\t"
        "fma.rn.f32x2 rd, ra, rb, rc;\n\t"
        "mov.b64 {%0,%1}, rd;\n\t}"
        : "=f"(d.x), "=f"(d.y)
        : "f"(a.x), "f"(a.y), "f"(b.x), "f"(b.y), "f"(c.x), "f"(c.y));
    return d;
}
static __forceinline__ __device__ float2 shfl_up2(float2 v, int delta) {
    float2 r;
    r.x = __shfl_up_sync(0xffffffffu, v.x, delta);
    r.y = __shfl_up_sync(0xffffffffu, v.y, delta);
    return r;
}
static __forceinline__ __device__ float2 shfl_dn2(float2 v, int delta) {
    float2 r;
    r.x = __shfl_down_sync(0xffffffffu, v.x, delta);
    r.y = __shfl_down_sync(0xffffffffu, v.y, delta);
    return r;
}

__global__ void __launch_bounds__(128, 6)
pde_kernel(const float* __restrict__ u0,
           const float* __restrict__ aw1, const float* __restrict__ aw2,
           const float* __restrict__ aw3, const float* __restrict__ bw1,
           const float* __restrict__ bw2, const float* __restrict__ bw3,
           float* __restrict__ out)
{
    // seam buffers: warp w's top row (grid row 12w) and bottom row (12w+11)
    __shared__ float2 stop[2][4][24];
    __shared__ float2 sbot[2][4][24];

    const int tid  = threadIdx.x;
    const int w    = tid >> 5;         // warp 0..3 -> rows 12w..12w+11
    const int lane = tid & 31;
    const int tcol = lane & 7;         // 0..7 -> cols 6*tcol..6*tcol+5
    const int trow = lane >> 3;        // 0..3 -> local rows 3*trow..3*trow+2
    const int row0 = 12 * w + 3 * trow;
    const int b    = blockIdx.x;

    const float2* g2 = (const float2*)(u0  + (size_t)b * (NXY * NXY));
    float2*       o2 = (float2*)      (out + (size_t)b * (NXY * NXY));

    // ---- coefficients ----
    const float TWO_PI = 6.283185307179586f;
    const float scale  = 1e-4f * 2304.0f;     // DT / DX^2
    const float inv47  = 1.0f / 47.0f;
    const float aa1 = fabsf(*aw1), aa2 = fabsf(*aw2), aa3 = fabsf(*aw3);
    const float bb1 = fabsf(*bw1), bb2 = fabsf(*bw2), bb3 = fabsf(*bw3);

    float2 a2[3];                      // alpha per local row (duplicated)
    #pragma unroll
    for (int r = 0; r < 3; r++) {
        float yv = (float)(row0 + r) * inv47;
        float al = 0.5f * scale * (aa1 + aa2 * sinf(TWO_PI * yv) + aa3 * cosf(TWO_PI * yv));
        a2[r] = make_float2(al, al);
    }
    float2 b2c[3];                     // beta per col pair
    #pragma unroll
    for (int p = 0; p < 3; p++) {
        float x0 = (float)(6 * tcol + 2 * p)     * inv47;
        float x1 = (float)(6 * tcol + 2 * p + 1) * inv47;
        b2c[p].x = scale * (bb1 + bb2 * cosf(TWO_PI * x0) + bb3 * sinf(TWO_PI * x0));
        b2c[p].y = scale * (bb1 + bb2 * cosf(TWO_PI * x1) + bb3 * sinf(TWO_PI * x1));
    }
    const float2 m2 = make_float2(-2.0f, -2.0f);

    // ---- load 3x6 cells ----
    float2 v[3][3];
    #pragma unroll
    for (int r = 0; r < 3; r++)
        #pragma unroll
        for (int p = 0; p < 3; p++)
            v[r][p] = g2[(row0 + r) * 24 + tcol * 3 + p];

    // ---- frozen reflected boundary (initial values) ----
    // top pad = u0 row 1: applies to (w0,trow0) whose local row 1 IS grid row 1.
    // bottom pad = u0 row 46: applies to (w3,trow3) whose local row 1 IS row 46.
    float2 fv[3];
    #pragma unroll
    for (int p = 0; p < 3; p++) fv[p] = v[1][p];
    float fh[3];
    #pragma unroll
    for (int r = 0; r < 3; r++) fh[r] = (tcol == 0) ? v[r][0].y : v[r][2].x;

    const bool topEdge = (w == 0) && (trow == 0);
    const bool botEdge = (w == 3) && (trow == 3);
    const bool isL = (tcol == 0), isR = (tcol == 7);
    const int  sidx = tcol * 3;

    // ---- time loop ----
    #pragma unroll 2
    for (int t = 0; t < NT; t++) {
        const int buf = t & 1;
        // publish warp seam rows (OLD state)
        if (trow == 0) {
            stop[buf][w][sidx] = v[0][0]; stop[buf][w][sidx+1] = v[0][1]; stop[buf][w][sidx+2] = v[0][2];
        }
        if (trow == 3) {
            sbot[buf][w][sidx] = v[2][0]; sbot[buf][w][sidx+1] = v[2][1]; sbot[buf][w][sidx+2] = v[2][2];
        }
        __syncthreads();

        // vertical halos (OLD state)
        float2 th[3], bh[3];
        #pragma unroll
        for (int p = 0; p < 3; p++) {
            float2 tu = shfl_up2(v[2][p], 8);     // lane-8's local row 2
            float2 bd = shfl_dn2(v[0][p], 8);     // lane+8's local row 0
            th[p] = (trow == 0) ? (topEdge ? fv[p] : stop[buf][w][sidx+p] /*placeholder*/) : tu;
            bh[p] = (trow == 3) ? (botEdge ? fv[p] : sbot[buf][w][sidx+p] /*placeholder*/) : bd;
        }
        // fix seam reads: trow0 reads bot of warp w-1; trow3 reads top of warp w+1
        if (trow == 0 && !topEdge) {
            #pragma unroll
            for (int p = 0; p < 3; p++) th[p] = sbot[buf][w - 1][sidx + p];
        }
        if (trow == 3 && !botEdge) {
            #pragma unroll
            for (int p = 0; p < 3; p++) bh[p] = stop[buf][w + 1][sidx + p];
        }

        // lateral halos
        float lh[3], rh[3];
        #pragma unroll
        for (int r = 0; r < 3; r++) {
            float lu = __shfl_up_sync(0xffffffffu, v[r][2].y, 1);
            float rd = __shfl_down_sync(0xffffffffu, v[r][0].x, 1);
            lh[r] = isL ? fh[r] : lu;
            rh[r] = isR ? fh[r] : rd;
        }

        // update: res = cur + a*(up+dn-2c) + b*(lf+rt-2c)
        float2 oldprev[3];
        #pragma unroll
        for (int p = 0; p < 3; p++) oldprev[p] = th[p];
        #pragma unroll
        for (int r = 0; r < 3; r++) {
            float x0 = v[r][0].x, x1 = v[r][0].y, x2 = v[r][1].x;
            float x3 = v[r][1].y, x4 = v[r][2].x, x5 = v[r][2].y;
            float s0 = lh[r] + x1, s1 = x0 + x2, s2 = x1 + x3;
            float s3 = x2 + x4,    s4 = x3 + x5, s5 = x4 + rh[r];

            #pragma unroll
            for (int p = 0; p < 3; p++) {
                float2 cur = v[r][p];
                float2 dn  = (r == 2) ? bh[p] : v[r + 1][p];
                float2 vs  = f2add(oldprev[p], dn);               // up + dn
                float2 hs  = (p == 0) ? make_float2(s0, s1)
                           : (p == 1) ? make_float2(s2, s3)
                                      : make_float2(s4, s5);
                vs = f2fma(m2, cur, vs);                          // up+dn-2c
                hs = f2fma(m2, cur, hs);                          // lf+rt-2c
                float2 res = f2fma(b2c[p], hs, cur);              // c + b*hs
                res = f2fma(a2[r], vs, res);                      // + a*vs
                oldprev[p] = cur;
                v[r][p] = res;
            }
        }
    }

    // ---- store ----
    #pragma unroll
    for (int r = 0; r < 3; r++)
        #pragma unroll
        for (int p = 0; p < 3; p++)
            o2[(row0 + r) * 24 + tcol * 3 + p] = v[r][p];
}

extern "C" void kernel_launch(void* const* d_in, const int* in_sizes, int n_in,
                              void* d_out, int out_size)
{
    const float* u0 = (const float*)d_in[0];
    int batches = in_sizes[0] / (NXY * NXY);
    pde_kernel<<<batches, 128>>>(u0,
        (const float*)d_in[1], (const float*)d_in[2], (const float*)d_in[3],
        (const float*)d_in[4], (const float*)d_in[5], (const float*)d_in[6],
        (float*)d_out);
}